// round 1
// baseline (speedup 1.0000x reference)
#include <cuda_runtime.h>
#include <cuda_bf16.h>
#include <cstddef>

// ---------------------------------------------------------------------------
// Problem constants
// ---------------------------------------------------------------------------
#define Bb     2
#define Tt     2048
#define Dm     1024
#define Hh     16
#define Dh     64
#define ROWS   (Bb * Tt)        // 4096
#define QKV_N  (3 * Dm)         // 3072

// Scratch (allocation-free: device globals)
__device__ float g_qkv[ROWS * QKV_N];    // [B*T, 3*Dm]
__device__ float g_attn[ROWS * Dm];      // [B*T, Dm]  (already merged-head layout)

// ---------------------------------------------------------------------------
// SGEMM: C[M,N] = A[M,K] @ B[K,N], all row-major, fp32.
// 128x128 block tile, BK=8, 256 threads, 8x8 per thread.
// Requires M%128==0, N%128==0, K%8==0 (true for all our shapes).
// ---------------------------------------------------------------------------
__global__ __launch_bounds__(256) void sgemm_kernel(
    const float* __restrict__ A, const float* __restrict__ B,
    float* __restrict__ C, int M, int N, int K)
{
    __shared__ float As[8][128];   // transposed A tile: As[k][m]
    __shared__ float Bs[8][128];   // Bs[k][n]

    const int tid = threadIdx.x;
    const int bx = blockIdx.x, by = blockIdx.y;
    const int tx = tid & 15, ty = tid >> 4;

    const int aRow = tid >> 1;            // 0..127
    const int aCol = (tid & 1) << 2;      // 0 or 4
    const int bRow = tid >> 5;            // 0..7
    const int bCol = (tid & 31) << 2;     // 0..124

    const float* Ablk = A + (size_t)(by * 128) * K;
    const float* Bblk = B + bx * 128;

    float acc[8][8];
#pragma unroll
    for (int i = 0; i < 8; i++)
#pragma unroll
        for (int j = 0; j < 8; j++) acc[i][j] = 0.f;

    for (int k0 = 0; k0 < K; k0 += 8) {
        float4 av = *(const float4*)(Ablk + (size_t)aRow * K + k0 + aCol);
        As[aCol + 0][aRow] = av.x;
        As[aCol + 1][aRow] = av.y;
        As[aCol + 2][aRow] = av.z;
        As[aCol + 3][aRow] = av.w;
        float4 bv = *(const float4*)(Bblk + (size_t)(k0 + bRow) * N + bCol);
        *(float4*)&Bs[bRow][bCol] = bv;
        __syncthreads();

#pragma unroll
        for (int k = 0; k < 8; k++) {
            float ra[8], rb[8];
            *(float4*)&ra[0] = *(const float4*)&As[k][ty * 4];
            *(float4*)&ra[4] = *(const float4*)&As[k][64 + ty * 4];
            *(float4*)&rb[0] = *(const float4*)&Bs[k][tx * 4];
            *(float4*)&rb[4] = *(const float4*)&Bs[k][64 + tx * 4];
#pragma unroll
            for (int i = 0; i < 8; i++)
#pragma unroll
                for (int j = 0; j < 8; j++)
                    acc[i][j] = fmaf(ra[i], rb[j], acc[i][j]);
        }
        __syncthreads();
    }

#pragma unroll
    for (int i = 0; i < 8; i++) {
        int r = by * 128 + ((i < 4) ? (ty * 4 + i) : (64 + ty * 4 + i - 4));
        float* Crow = C + (size_t)r * N + bx * 128;
        float4 v0 = make_float4(acc[i][0], acc[i][1], acc[i][2], acc[i][3]);
        float4 v1 = make_float4(acc[i][4], acc[i][5], acc[i][6], acc[i][7]);
        *(float4*)(Crow + tx * 4) = v0;
        *(float4*)(Crow + 64 + tx * 4) = v1;
    }
}

// ---------------------------------------------------------------------------
// Flash-attention (causal), fp32.
// Grid: (T/64, H, B). Block: 256 threads (16x16), 4x4 micro-tile.
// Smem: Qt[d][i], KP (Kt[d][j] aliased with Pt[j][i]), Vs[j][d]; PAD=68 keeps
// all float4 LDS paths 16B-aligned and spreads banks.
// Writes output directly in merged [B*T, Dm] layout.
// ---------------------------------------------------------------------------
#define PAD 68
#define ATTN_SMEM_BYTES ((3 * 64 * PAD + 3 * 64) * (int)sizeof(float))

__global__ __launch_bounds__(256) void attn_kernel(
    const float* __restrict__ qkv, float* __restrict__ out)
{
    extern __shared__ float sm[];
    float* Qt   = sm;                  // [64][PAD]  Qt[d][i]
    float* KP   = Qt + 64 * PAD;       // Kt[d][j]  /  Pt[j][i] (aliased)
    float* Vs   = KP + 64 * PAD;       // Vs[j][d]
    float* mrow = Vs + 64 * PAD;       // [64]
    float* lrow = mrow + 64;           // [64]
    float* arow = lrow + 64;           // [64]

    const int qb = blockIdx.x;
    const int h  = blockIdx.y;
    const int b  = blockIdx.z;
    const int tid = threadIdx.x;
    const int tx = tid & 15, ty = tid >> 4;
    const int i0 = ty << 2, j0 = tx << 2;
    const int RS = QKV_N;  // 3072 row stride in qkv

    // --- load Q tile (scaled by 1/sqrt(Dh)=0.125), transposed -> Qt[d][i]
    const float* qbase = qkv + ((size_t)(b * Tt + qb * 64)) * RS + h * Dh;
#pragma unroll
    for (int it = 0; it < 4; it++) {
        int idx = tid + it * 256;
        int r = idx >> 4;
        int c = (idx & 15) << 2;
        float4 v = *(const float4*)(qbase + (size_t)r * RS + c);
        Qt[(c + 0) * PAD + r] = v.x * 0.125f;
        Qt[(c + 1) * PAD + r] = v.y * 0.125f;
        Qt[(c + 2) * PAD + r] = v.z * 0.125f;
        Qt[(c + 3) * PAD + r] = v.w * 0.125f;
    }
    if (tid < 64) { mrow[tid] = -1e30f; lrow[tid] = 0.f; }

    float O[4][4] = {};
    const float* kbase0 = qkv + ((size_t)(b * Tt)) * RS + Dm + h * Dh;
    const float* vbase0 = kbase0 + Dm;

    for (int kb = 0; kb <= qb; kb++) {
        __syncthreads();  // Q ready (kb=0) / previous PV done (kb>0)

        const float* kbase = kbase0 + (size_t)(kb * 64) * RS;
        const float* vbase = vbase0 + (size_t)(kb * 64) * RS;
#pragma unroll
        for (int it = 0; it < 4; it++) {
            int idx = tid + it * 256;
            int r = idx >> 4;
            int c = (idx & 15) << 2;
            float4 kv = *(const float4*)(kbase + (size_t)r * RS + c);
            KP[(c + 0) * PAD + r] = kv.x;
            KP[(c + 1) * PAD + r] = kv.y;
            KP[(c + 2) * PAD + r] = kv.z;
            KP[(c + 3) * PAD + r] = kv.w;
            float4 vv = *(const float4*)(vbase + (size_t)r * RS + c);
            *(float4*)(Vs + r * PAD + c) = vv;
        }
        __syncthreads();

        // --- S = Q @ K^T (scaled)
        float S[4][4] = {};
#pragma unroll 8
        for (int d = 0; d < 64; d++) {
            float4 qa = *(const float4*)(Qt + d * PAD + i0);
            float4 kv = *(const float4*)(KP + d * PAD + j0);
            float qr[4] = {qa.x, qa.y, qa.z, qa.w};
            float kr[4] = {kv.x, kv.y, kv.z, kv.w};
#pragma unroll
            for (int ii = 0; ii < 4; ii++)
#pragma unroll
                for (int jj = 0; jj < 4; jj++)
                    S[ii][jj] = fmaf(qr[ii], kr[jj], S[ii][jj]);
        }
        if (kb == qb) {
#pragma unroll
            for (int ii = 0; ii < 4; ii++)
#pragma unroll
                for (int jj = 0; jj < 4; jj++)
                    if (j0 + jj > i0 + ii) S[ii][jj] = -1e30f;
        }
        __syncthreads();  // everyone done reading Kt before overwrite as Pt

        // --- write S transposed: Pt[j][i]
#pragma unroll
        for (int jj = 0; jj < 4; jj++)
#pragma unroll
            for (int ii = 0; ii < 4; ii++)
                KP[(j0 + jj) * PAD + (i0 + ii)] = S[ii][jj];
        __syncthreads();

        // --- online softmax per row (threads 0..63, one row each)
        if (tid < 64) {
            int r = tid;
            float m_old = mrow[r];
            float mx = m_old;
#pragma unroll 8
            for (int j = 0; j < 64; j++) mx = fmaxf(mx, KP[j * PAD + r]);
            float a = __expf(m_old - mx);
            float s = 0.f;
#pragma unroll 8
            for (int j = 0; j < 64; j++) {
                float p = __expf(KP[j * PAD + r] - mx);
                KP[j * PAD + r] = p;
                s += p;
            }
            lrow[r] = lrow[r] * a + s;
            mrow[r] = mx;
            arow[r] = a;
        }
        __syncthreads();

        // --- rescale O and accumulate P @ V
        {
            float a0 = arow[i0 + 0], a1 = arow[i0 + 1],
                  a2 = arow[i0 + 2], a3 = arow[i0 + 3];
#pragma unroll
            for (int dd = 0; dd < 4; dd++) {
                O[0][dd] *= a0; O[1][dd] *= a1; O[2][dd] *= a2; O[3][dd] *= a3;
            }
        }
#pragma unroll 8
        for (int j = 0; j < 64; j++) {
            float4 p  = *(const float4*)(KP + j * PAD + i0);
            float4 vv = *(const float4*)(Vs + j * PAD + j0);
            float pr[4] = {p.x, p.y, p.z, p.w};
            float vr[4] = {vv.x, vv.y, vv.z, vv.w};
#pragma unroll
            for (int ii = 0; ii < 4; ii++)
#pragma unroll
                for (int dd = 0; dd < 4; dd++)
                    O[ii][dd] = fmaf(pr[ii], vr[dd], O[ii][dd]);
        }
    }

    // --- epilogue: normalize, store merged-head layout [B*T, Dm]
    float* obase = out + ((size_t)(b * Tt + qb * 64)) * Dm + h * Dh;
#pragma unroll
    for (int ii = 0; ii < 4; ii++) {
        float inv = 1.0f / lrow[i0 + ii];
        float4 v = make_float4(O[ii][0] * inv, O[ii][1] * inv,
                               O[ii][2] * inv, O[ii][3] * inv);
        *(float4*)(obase + (size_t)(i0 + ii) * Dm + j0) = v;
    }
}

// ---------------------------------------------------------------------------
// Launch
// ---------------------------------------------------------------------------
extern "C" void kernel_launch(void* const* d_in, const int* in_sizes, int n_in,
                              void* d_out, int out_size)
{
    (void)in_sizes; (void)n_in; (void)out_size;
    const float* x      = (const float*)d_in[0];
    // d_in[1] = mask (deterministically causal; hardcoded in attn_kernel)
    const float* w_qkv  = (const float*)d_in[2];
    const float* w_out  = (const float*)d_in[3];
    float* out          = (float*)d_out;

    float* qkv = nullptr;
    float* attn = nullptr;
    cudaGetSymbolAddress((void**)&qkv, g_qkv);
    cudaGetSymbolAddress((void**)&attn, g_attn);

    cudaFuncSetAttribute(attn_kernel,
                         cudaFuncAttributeMaxDynamicSharedMemorySize,
                         ATTN_SMEM_BYTES);

    // 1) QKV projection: [4096,1024] @ [1024,3072]
    sgemm_kernel<<<dim3(QKV_N / 128, ROWS / 128), 256>>>(
        x, w_qkv, qkv, ROWS, QKV_N, Dm);

    // 2) causal flash attention per (b, h, q-tile)
    attn_kernel<<<dim3(Tt / 64, Hh, Bb), 256, ATTN_SMEM_BYTES>>>(qkv, attn);

    // 3) output projection: [4096,1024] @ [1024,1024]
    sgemm_kernel<<<dim3(Dm / 128, ROWS / 128), 256>>>(
        attn, w_out, out, ROWS, Dm, Dm);
}